// round 14
// baseline (speedup 1.0000x reference)
#include <cuda_runtime.h>

#define TT 100
#define BB 32768

// ---- frozen arithmetic (R5/R8/R13, passing, rel_err 5.5296e-4) ----
// Per neuron: NEON 4-lane dot as 2x f32x2 chains over float4 groups,
// pairwise reduce (l0+l1)+(l2+l3), scalar fma tail, bias after,
// LIF: fmaf(0.9,m,cur) - reset (reset from PREVIOUS mem), spike = nm>1.

typedef unsigned long long u64;

__device__ __forceinline__ u64 fma2(u64 a, u64 b, u64 c) {
    u64 d;
    asm("fma.rn.f32x2 %0, %1, %2, %3;" : "=l"(d) : "l"(a), "l"(b), "l"(c));
    return d;
}

__device__ __forceinline__ float reduce2x2(u64 a01, u64 a23) {
    float l0, l1, l2, l3;
    asm("mov.b64 {%0,%1}, %2;" : "=f"(l0), "=f"(l1) : "l"(a01));
    asm("mov.b64 {%0,%1}, %2;" : "=f"(l2), "=f"(l3) : "l"(a23));
    return __fadd_rn(__fadd_rn(l0, l1), __fadd_rn(l2, l3));
}

__global__ __launch_bounds__(32) void snn_kernel(
    const float* __restrict__ x,
    const float* __restrict__ w_s1, const float* __restrict__ b_s1,
    const float* __restrict__ w_s2, const float* __restrict__ b_s2,
    const float* __restrict__ w_c1, const float* __restrict__ b_c1,
    const float* __restrict__ w_co, const float* __restrict__ b_co,
    const float* __restrict__ w_ro, const float* __restrict__ b_ro,
    float* __restrict__ out)
{
    __shared__ __align__(16) float s_ws1[28 * 32];
    __shared__ __align__(16) float s_ws2[14 * 28];
    __shared__ __align__(16) float s_wc1[8 * 16];
    __shared__ __align__(16) float s_wco[3 * 8];
    __shared__ __align__(16) float s_wro[16];
    __shared__ float s_bs1[28], s_bs2[14], s_bc1[8], s_bco[3], s_bro[1];
    // membranes paired: [neuron_pair][lane(el0)=0..31 | lane+32(el1)]
    __shared__ __align__(8) float2 s_m1p[14][64];
    __shared__ __align__(8) float2 s_m2p[7][64];
    __shared__ __align__(8) float2 s_mc1p[4][64];

    const int tid = threadIdx.x;
    for (int i = tid; i < 28 * 32; i += 32) s_ws1[i] = w_s1[i];
    for (int i = tid; i < 14 * 28; i += 32) s_ws2[i] = w_s2[i];
    for (int i = tid; i < 8 * 16;  i += 32) s_wc1[i] = (i % 16 < 14) ? w_c1[(i / 16) * 14 + (i % 16)] : 0.0f;
    for (int i = tid; i < 3 * 8;   i += 32) s_wco[i] = w_co[i];
    if (tid < 16) s_wro[tid] = (tid < 14) ? w_ro[tid] : 0.0f;
    for (int i = tid; i < 28; i += 32) s_bs1[i] = b_s1[i];
    for (int i = tid; i < 14; i += 32) s_bs2[i] = b_s2[i];
    for (int i = tid; i < 8;  i += 32) s_bc1[i] = b_c1[i];
    for (int i = tid; i < 3;  i += 32) s_bco[i] = b_co[i];
    if (tid == 0) s_bro[0] = b_ro[0];

    for (int k = 0; k < 14; k++) { s_m1p[k][tid] = make_float2(0.f, 0.f); s_m1p[k][tid + 32] = make_float2(0.f, 0.f); }
    for (int k = 0; k < 7;  k++) { s_m2p[k][tid] = make_float2(0.f, 0.f); s_m2p[k][tid + 32] = make_float2(0.f, 0.f); }
    for (int k = 0; k < 4;  k++) { s_mc1p[k][tid] = make_float2(0.f, 0.f); s_mc1p[k][tid + 32] = make_float2(0.f, 0.f); }
    float mcoA0 = 0.f, mcoA1 = 0.f, mcoA2 = 0.f, mroA = 0.f;
    float mcoB0 = 0.f, mcoB1 = 0.f, mcoB2 = 0.f, mroB = 0.f;
    __syncthreads();

    const int e0 = blockIdx.x * 64 + tid;   // element A
    const int e1 = e0 + 32;                 // element B

    float* o_mco   = out;                          // (T,B,3)
    float* o_spkc1 = out + (size_t)TT * BB * 3;    // (T,B,8)
    float* o_mro   = out + (size_t)TT * BB * 11;   // (T,B,1)
    float* o_spk1  = out + (size_t)TT * BB * 12;   // (T,B,28)
    float* o_spk2  = out + (size_t)TT * BB * 40;   // (T,B,14)

    // x for t=0, both elements (packed 16B groups: .x=(f0,f1) .y=(f2,f3))
    ulonglong2 xva[8], xvb[8];
    {
        const ulonglong2* xa = (const ulonglong2*)(x + (size_t)e0 * 32);
        const ulonglong2* xb = (const ulonglong2*)(x + (size_t)e1 * 32);
        #pragma unroll
        for (int i = 0; i < 8; i++) { xva[i] = xa[i]; xvb[i] = xb[i]; }
    }

    #pragma unroll 1
    for (int t = 0; t < TT; t++) {
        const size_t base0 = (size_t)t * BB + e0;
        const size_t base1 = (size_t)t * BB + e1;

        // ---- layer s1: 32 -> 28, neuron pairs x 2 elements ----
        unsigned bits1A = 0, bits1B = 0;
        #pragma unroll 7
        for (int k = 0; k < 14; k++) {
            const int j0 = 2 * k, j1 = 2 * k + 1;
            const ulonglong2* wr0 = (const ulonglong2*)&s_ws1[j0 * 32];
            const ulonglong2* wr1 = (const ulonglong2*)&s_ws1[j1 * 32];
            u64 aA = 0, bA = 0, cA = 0, dA = 0, aB = 0, bB = 0, cB = 0, dB = 0;
            #pragma unroll
            for (int i = 0; i < 8; i++) {
                ulonglong2 w0 = wr0[i];
                ulonglong2 w1 = wr1[i];
                aA = fma2(w0.x, xva[i].x, aA);  bA = fma2(w0.y, xva[i].y, bA);
                cA = fma2(w1.x, xva[i].x, cA);  dA = fma2(w1.y, xva[i].y, dA);
                aB = fma2(w0.x, xvb[i].x, aB);  bB = fma2(w0.y, xvb[i].y, bB);
                cB = fma2(w1.x, xvb[i].x, cB);  dB = fma2(w1.y, xvb[i].y, dB);
            }
            float c0A = __fadd_rn(reduce2x2(aA, bA), s_bs1[j0]);
            float c1A = __fadd_rn(reduce2x2(cA, dA), s_bs1[j1]);
            float c0B = __fadd_rn(reduce2x2(aB, bB), s_bs1[j0]);
            float c1B = __fadd_rn(reduce2x2(cB, dB), s_bs1[j1]);
            float2 mA = s_m1p[k][tid];
            float2 mB = s_m1p[k][tid + 32];
            float n0A = __fadd_rn(fmaf(0.9f, mA.x, c0A), -((mA.x > 1.0f) ? 1.0f : 0.0f));
            float n1A = __fadd_rn(fmaf(0.9f, mA.y, c1A), -((mA.y > 1.0f) ? 1.0f : 0.0f));
            float n0B = __fadd_rn(fmaf(0.9f, mB.x, c0B), -((mB.x > 1.0f) ? 1.0f : 0.0f));
            float n1B = __fadd_rn(fmaf(0.9f, mB.y, c1B), -((mB.y > 1.0f) ? 1.0f : 0.0f));
            s_m1p[k][tid]      = make_float2(n0A, n1A);
            s_m1p[k][tid + 32] = make_float2(n0B, n1B);
            bits1A |= ((n0A > 1.0f) ? 1u : 0u) << j0;
            bits1A |= ((n1A > 1.0f) ? 1u : 0u) << j1;
            bits1B |= ((n0B > 1.0f) ? 1u : 0u) << j0;
            bits1B |= ((n1B > 1.0f) ? 1u : 0u) << j1;
        }

        float spk1A[28], spk1B[28];
        #pragma unroll
        for (int i = 0; i < 28; i++) {
            spk1A[i] = ((bits1A >> i) & 1u) ? 1.0f : 0.0f;
            spk1B[i] = ((bits1B >> i) & 1u) ? 1.0f : 0.0f;
        }

        // ---- reload x for t+1 (xva/xvb now dead; overlaps s2..ro compute) ----
        {
            int tn = (t + 1 < TT) ? (t + 1) : (TT - 1);
            const ulonglong2* xa = (const ulonglong2*)(x + ((size_t)tn * BB + e0) * 32);
            const ulonglong2* xb = (const ulonglong2*)(x + ((size_t)tn * BB + e1) * 32);
            #pragma unroll
            for (int i = 0; i < 8; i++) { xva[i] = xa[i]; xvb[i] = xb[i]; }
        }

        // ---- layer s2: 28 -> 14 ----
        unsigned bits2A = 0, bits2B = 0;
        #pragma unroll 7
        for (int k = 0; k < 7; k++) {
            const int j0 = 2 * k, j1 = 2 * k + 1;
            const ulonglong2* wr0 = (const ulonglong2*)&s_ws2[j0 * 28];
            const ulonglong2* wr1 = (const ulonglong2*)&s_ws2[j1 * 28];
            const ulonglong2* vA = (const ulonglong2*)spk1A;
            const ulonglong2* vB = (const ulonglong2*)spk1B;
            u64 aA = 0, bA = 0, cA = 0, dA = 0, aB = 0, bB = 0, cB = 0, dB = 0;
            #pragma unroll
            for (int i = 0; i < 7; i++) {
                ulonglong2 w0 = wr0[i];
                ulonglong2 w1 = wr1[i];
                aA = fma2(w0.x, vA[i].x, aA);  bA = fma2(w0.y, vA[i].y, bA);
                cA = fma2(w1.x, vA[i].x, cA);  dA = fma2(w1.y, vA[i].y, dA);
                aB = fma2(w0.x, vB[i].x, aB);  bB = fma2(w0.y, vB[i].y, bB);
                cB = fma2(w1.x, vB[i].x, cB);  dB = fma2(w1.y, vB[i].y, dB);
            }
            float c0A = __fadd_rn(reduce2x2(aA, bA), s_bs2[j0]);
            float c1A = __fadd_rn(reduce2x2(cA, dA), s_bs2[j1]);
            float c0B = __fadd_rn(reduce2x2(aB, bB), s_bs2[j0]);
            float c1B = __fadd_rn(reduce2x2(cB, dB), s_bs2[j1]);
            float2 mA = s_m2p[k][tid];
            float2 mB = s_m2p[k][tid + 32];
            float n0A = __fadd_rn(fmaf(0.9f, mA.x, c0A), -((mA.x > 1.0f) ? 1.0f : 0.0f));
            float n1A = __fadd_rn(fmaf(0.9f, mA.y, c1A), -((mA.y > 1.0f) ? 1.0f : 0.0f));
            float n0B = __fadd_rn(fmaf(0.9f, mB.x, c0B), -((mB.x > 1.0f) ? 1.0f : 0.0f));
            float n1B = __fadd_rn(fmaf(0.9f, mB.y, c1B), -((mB.y > 1.0f) ? 1.0f : 0.0f));
            s_m2p[k][tid]      = make_float2(n0A, n1A);
            s_m2p[k][tid + 32] = make_float2(n0B, n1B);
            bits2A |= ((n0A > 1.0f) ? 1u : 0u) << j0;
            bits2A |= ((n1A > 1.0f) ? 1u : 0u) << j1;
            bits2B |= ((n0B > 1.0f) ? 1u : 0u) << j0;
            bits2B |= ((n1B > 1.0f) ? 1u : 0u) << j1;
        }

        float spk2A[14], spk2B[14];
        #pragma unroll
        for (int i = 0; i < 14; i++) {
            spk2A[i] = ((bits2A >> i) & 1u) ? 1.0f : 0.0f;
            spk2B[i] = ((bits2B >> i) & 1u) ? 1.0f : 0.0f;
        }

        // ---- layer c1: 14 -> 8 (3 vec groups + tail 12,13) ----
        unsigned bitscA = 0, bitscB = 0;
        #pragma unroll
        for (int k = 0; k < 4; k++) {
            const int j0 = 2 * k, j1 = 2 * k + 1;
            const ulonglong2* wr0 = (const ulonglong2*)&s_wc1[j0 * 16];
            const ulonglong2* wr1 = (const ulonglong2*)&s_wc1[j1 * 16];
            const ulonglong2* vA = (const ulonglong2*)spk2A;
            const ulonglong2* vB = (const ulonglong2*)spk2B;
            u64 aA = 0, bA = 0, cA = 0, dA = 0, aB = 0, bB = 0, cB = 0, dB = 0;
            #pragma unroll
            for (int i = 0; i < 3; i++) {
                ulonglong2 w0 = wr0[i];
                ulonglong2 w1 = wr1[i];
                aA = fma2(w0.x, vA[i].x, aA);  bA = fma2(w0.y, vA[i].y, bA);
                cA = fma2(w1.x, vA[i].x, cA);  dA = fma2(w1.y, vA[i].y, dA);
                aB = fma2(w0.x, vB[i].x, aB);  bB = fma2(w0.y, vB[i].y, bB);
                cB = fma2(w1.x, vB[i].x, cB);  dB = fma2(w1.y, vB[i].y, dB);
            }
            float s0A = reduce2x2(aA, bA), s1A = reduce2x2(cA, dA);
            float s0B = reduce2x2(aB, bB), s1B = reduce2x2(cB, dB);
            s0A = fmaf(s_wc1[j0 * 16 + 12], spk2A[12], s0A);
            s0A = fmaf(s_wc1[j0 * 16 + 13], spk2A[13], s0A);
            s1A = fmaf(s_wc1[j1 * 16 + 12], spk2A[12], s1A);
            s1A = fmaf(s_wc1[j1 * 16 + 13], spk2A[13], s1A);
            s0B = fmaf(s_wc1[j0 * 16 + 12], spk2B[12], s0B);
            s0B = fmaf(s_wc1[j0 * 16 + 13], spk2B[13], s0B);
            s1B = fmaf(s_wc1[j1 * 16 + 12], spk2B[12], s1B);
            s1B = fmaf(s_wc1[j1 * 16 + 13], spk2B[13], s1B);
            float c0A = __fadd_rn(s0A, s_bc1[j0]);
            float c1A = __fadd_rn(s1A, s_bc1[j1]);
            float c0B = __fadd_rn(s0B, s_bc1[j0]);
            float c1B = __fadd_rn(s1B, s_bc1[j1]);
            float2 mA = s_mc1p[k][tid];
            float2 mB = s_mc1p[k][tid + 32];
            float n0A = __fadd_rn(fmaf(0.9f, mA.x, c0A), -((mA.x > 1.0f) ? 1.0f : 0.0f));
            float n1A = __fadd_rn(fmaf(0.9f, mA.y, c1A), -((mA.y > 1.0f) ? 1.0f : 0.0f));
            float n0B = __fadd_rn(fmaf(0.9f, mB.x, c0B), -((mB.x > 1.0f) ? 1.0f : 0.0f));
            float n1B = __fadd_rn(fmaf(0.9f, mB.y, c1B), -((mB.y > 1.0f) ? 1.0f : 0.0f));
            s_mc1p[k][tid]      = make_float2(n0A, n1A);
            s_mc1p[k][tid + 32] = make_float2(n0B, n1B);
            bitscA |= ((n0A > 1.0f) ? 1u : 0u) << j0;
            bitscA |= ((n1A > 1.0f) ? 1u : 0u) << j1;
            bitscB |= ((n0B > 1.0f) ? 1u : 0u) << j0;
            bitscB |= ((n1B > 1.0f) ? 1u : 0u) << j1;
        }

        float spkcA[8], spkcB[8];
        #pragma unroll
        for (int i = 0; i < 8; i++) {
            spkcA[i] = ((bitscA >> i) & 1u) ? 1.0f : 0.0f;
            spkcB[i] = ((bitscB >> i) & 1u) ? 1.0f : 0.0f;
        }

        // ---- layer co: 8 -> 3 (mems in regs) ----
        #pragma unroll
        for (int j = 0; j < 3; j++) {
            const ulonglong2* wr = (const ulonglong2*)&s_wco[j * 8];
            const ulonglong2* vA = (const ulonglong2*)spkcA;
            const ulonglong2* vB = (const ulonglong2*)spkcB;
            u64 aA = 0, bA = 0, aB = 0, bB = 0;
            #pragma unroll
            for (int i = 0; i < 2; i++) {
                ulonglong2 w = wr[i];
                aA = fma2(w.x, vA[i].x, aA);  bA = fma2(w.y, vA[i].y, bA);
                aB = fma2(w.x, vB[i].x, aB);  bB = fma2(w.y, vB[i].y, bB);
            }
            float cA = __fadd_rn(reduce2x2(aA, bA), s_bco[j]);
            float cB = __fadd_rn(reduce2x2(aB, bB), s_bco[j]);
            float mA = (j == 0) ? mcoA0 : (j == 1) ? mcoA1 : mcoA2;
            float mB = (j == 0) ? mcoB0 : (j == 1) ? mcoB1 : mcoB2;
            float nA = __fadd_rn(fmaf(0.9f, mA, cA), -((mA > 1.0f) ? 1.0f : 0.0f));
            float nB = __fadd_rn(fmaf(0.9f, mB, cB), -((mB > 1.0f) ? 1.0f : 0.0f));
            if (j == 0) { mcoA0 = nA; mcoB0 = nB; }
            else if (j == 1) { mcoA1 = nA; mcoB1 = nB; }
            else { mcoA2 = nA; mcoB2 = nB; }
        }

        // ---- layer ro: 14 -> 1 ----
        {
            const ulonglong2* wr = (const ulonglong2*)s_wro;
            const ulonglong2* vA = (const ulonglong2*)spk2A;
            const ulonglong2* vB = (const ulonglong2*)spk2B;
            u64 aA = 0, bA = 0, aB = 0, bB = 0;
            #pragma unroll
            for (int i = 0; i < 3; i++) {
                ulonglong2 w = wr[i];
                aA = fma2(w.x, vA[i].x, aA);  bA = fma2(w.y, vA[i].y, bA);
                aB = fma2(w.x, vB[i].x, aB);  bB = fma2(w.y, vB[i].y, bB);
            }
            float sA = reduce2x2(aA, bA);
            float sB = reduce2x2(aB, bB);
            sA = fmaf(s_wro[12], spk2A[12], sA);
            sA = fmaf(s_wro[13], spk2A[13], sA);
            sB = fmaf(s_wro[12], spk2B[12], sB);
            sB = fmaf(s_wro[13], spk2B[13], sB);
            float cA = __fadd_rn(sA, s_bro[0]);
            float cB = __fadd_rn(sB, s_bro[0]);
            mroA = __fadd_rn(fmaf(0.9f, mroA, cA), -((mroA > 1.0f) ? 1.0f : 0.0f));
            mroB = __fadd_rn(fmaf(0.9f, mroB, cB), -((mroB > 1.0f) ? 1.0f : 0.0f));
        }

        // ---- stores, both elements (vectorized, coalesced) ----
        {
            float* pA = o_mco + base0 * 3;
            float* pB = o_mco + base1 * 3;
            pA[0] = mcoA0; pA[1] = mcoA1; pA[2] = mcoA2;
            pB[0] = mcoB0; pB[1] = mcoB1; pB[2] = mcoB2;
        }
        {
            float4* qA = (float4*)(o_spkc1 + base0 * 8);
            float4* qB = (float4*)(o_spkc1 + base1 * 8);
            qA[0] = make_float4(spkcA[0], spkcA[1], spkcA[2], spkcA[3]);
            qA[1] = make_float4(spkcA[4], spkcA[5], spkcA[6], spkcA[7]);
            qB[0] = make_float4(spkcB[0], spkcB[1], spkcB[2], spkcB[3]);
            qB[1] = make_float4(spkcB[4], spkcB[5], spkcB[6], spkcB[7]);
        }
        o_mro[base0] = mroA;
        o_mro[base1] = mroB;
        {
            float4* rA = (float4*)(o_spk1 + base0 * 28);
            float4* rB = (float4*)(o_spk1 + base1 * 28);
            #pragma unroll
            for (int j = 0; j < 7; j++) {
                rA[j] = make_float4(spk1A[4 * j], spk1A[4 * j + 1],
                                    spk1A[4 * j + 2], spk1A[4 * j + 3]);
                rB[j] = make_float4(spk1B[4 * j], spk1B[4 * j + 1],
                                    spk1B[4 * j + 2], spk1B[4 * j + 3]);
            }
        }
        {
            float2* sA = (float2*)(o_spk2 + base0 * 14);
            float2* sB = (float2*)(o_spk2 + base1 * 14);
            #pragma unroll
            for (int j = 0; j < 7; j++) {
                sA[j] = make_float2(spk2A[2 * j], spk2A[2 * j + 1]);
                sB[j] = make_float2(spk2B[2 * j], spk2B[2 * j + 1]);
            }
        }
    }
}

extern "C" void kernel_launch(void* const* d_in, const int* in_sizes, int n_in,
                              void* d_out, int out_size) {
    snn_kernel<<<BB / 64, 32>>>(
        (const float*)d_in[0],
        (const float*)d_in[1],  (const float*)d_in[2],
        (const float*)d_in[3],  (const float*)d_in[4],
        (const float*)d_in[5],  (const float*)d_in[6],
        (const float*)d_in[7],  (const float*)d_in[8],
        (const float*)d_in[9],  (const float*)d_in[10],
        (float*)d_out);
}

// round 15
// speedup vs baseline: 1.1546x; 1.1546x over previous
#include <cuda_runtime.h>

#define TT 100
#define BB 32768

// ---- frozen arithmetic (R5/R8/R13, passing, rel_err 5.5296e-4) ----
// Per neuron: NEON 4-lane dot as 2x f32x2 chains over float4 groups,
// pairwise reduce (l0+l1)+(l2+l3), scalar fma tail, bias after,
// LIF: fmaf(0.9,m,cur) - reset (reset from PREVIOUS mem), spike = nm>1.

typedef unsigned long long u64;

__device__ __forceinline__ u64 fma2(u64 a, u64 b, u64 c) {
    u64 d;
    asm("fma.rn.f32x2 %0, %1, %2, %3;" : "=l"(d) : "l"(a), "l"(b), "l"(c));
    return d;
}

__device__ __forceinline__ float reduce2x2(u64 a01, u64 a23) {
    float l0, l1, l2, l3;
    asm("mov.b64 {%0,%1}, %2;" : "=f"(l0), "=f"(l1) : "l"(a01));
    asm("mov.b64 {%0,%1}, %2;" : "=f"(l2), "=f"(l3) : "l"(a23));
    return __fadd_rn(__fadd_rn(l0, l1), __fadd_rn(l2, l3));
}

__global__ __launch_bounds__(64) void snn_kernel(
    const float* __restrict__ x,
    const float* __restrict__ w_s1, const float* __restrict__ b_s1,
    const float* __restrict__ w_s2, const float* __restrict__ b_s2,
    const float* __restrict__ w_c1, const float* __restrict__ b_c1,
    const float* __restrict__ w_co, const float* __restrict__ b_co,
    const float* __restrict__ w_ro, const float* __restrict__ b_ro,
    float* __restrict__ out)
{
    __shared__ __align__(16) float s_ws1[28 * 32];
    __shared__ __align__(16) float s_ws2[14 * 28];
    __shared__ __align__(16) float s_wc1[8 * 16];
    __shared__ __align__(16) float s_wco[3 * 8];
    __shared__ __align__(16) float s_wro[16];
    __shared__ float s_bs1[28], s_bs2[14], s_bc1[8], s_bco[3], s_bro[1];
    // packed-spike exchange buffers (one u32 per thread per layer)
    __shared__ unsigned s_b1[64], s_b2[64], s_bc[64];

    const int tid  = threadIdx.x;
    const int w    = tid >> 5;    // warp 0/1: neuron partition
    const int lane = tid & 31;    // element within the 32-element group

    for (int i = tid; i < 28 * 32; i += 64) s_ws1[i] = w_s1[i];
    for (int i = tid; i < 14 * 28; i += 64) s_ws2[i] = w_s2[i];
    for (int i = tid; i < 8 * 16;  i += 64) s_wc1[i] = (i % 16 < 14) ? w_c1[(i / 16) * 14 + (i % 16)] : 0.0f;
    for (int i = tid; i < 3 * 8;   i += 64) s_wco[i] = w_co[i];
    if (tid < 16) s_wro[tid] = (tid < 14) ? w_ro[tid] : 0.0f;
    for (int i = tid; i < 28; i += 64) s_bs1[i] = b_s1[i];
    for (int i = tid; i < 14; i += 64) s_bs2[i] = b_s2[i];
    for (int i = tid; i < 8;  i += 64) s_bc1[i] = b_c1[i];
    for (int i = tid; i < 3;  i += 64) s_bco[i] = b_co[i];
    if (tid == 0) s_bro[0] = b_ro[0];
    __syncthreads();

    const int b = blockIdx.x * 32 + lane;

    // owned membranes in REGISTERS (constant-indexed, fully unrolled loops)
    float m1[14], m2[7], mc1[4];
    #pragma unroll
    for (int k = 0; k < 14; k++) m1[k] = 0.0f;
    #pragma unroll
    for (int k = 0; k < 7;  k++) m2[k] = 0.0f;
    #pragma unroll
    for (int k = 0; k < 4;  k++) mc1[k] = 0.0f;
    float mco0 = 0.f, mco1 = 0.f, mco2 = 0.f;   // warp0 only
    float mro = 0.f;                             // warp1 only

    const int jb1 = 14 * w;   // s1 neuron base
    const int jb2 = 7 * w;    // s2 neuron base
    const int jbc = 4 * w;    // c1 neuron base

    float* o_mco   = out;                          // (T,B,3)
    float* o_spkc1 = out + (size_t)TT * BB * 3;    // (T,B,8)
    float* o_mro   = out + (size_t)TT * BB * 11;   // (T,B,1)
    float* o_spk1  = out + (size_t)TT * BB * 12;   // (T,B,28)
    float* o_spk2  = out + (size_t)TT * BB * 40;   // (T,B,14)

    // x for t=0 (packed 16B groups: .x=(f0,f1) .y=(f2,f3))
    ulonglong2 xv[8];
    {
        const ulonglong2* xt = (const ulonglong2*)(x + (size_t)b * 32);
        #pragma unroll
        for (int i = 0; i < 8; i++) xv[i] = xt[i];
    }

    #pragma unroll 1
    for (int t = 0; t < TT; t++) {
        const size_t base = (size_t)t * BB + b;

        // ---- layer s1: my 14 neurons (7 pairs) ----
        unsigned bits1 = 0;
        #pragma unroll
        for (int p = 0; p < 7; p++) {
            const int j0 = jb1 + 2 * p, j1 = j0 + 1;
            const ulonglong2* wr0 = (const ulonglong2*)&s_ws1[j0 * 32];
            const ulonglong2* wr1 = (const ulonglong2*)&s_ws1[j1 * 32];
            u64 a01 = 0, a23 = 0, b01 = 0, b23 = 0;
            #pragma unroll
            for (int i = 0; i < 8; i++) {
                ulonglong2 w0 = wr0[i];
                ulonglong2 w1 = wr1[i];
                a01 = fma2(w0.x, xv[i].x, a01);  a23 = fma2(w0.y, xv[i].y, a23);
                b01 = fma2(w1.x, xv[i].x, b01);  b23 = fma2(w1.y, xv[i].y, b23);
            }
            float c0 = __fadd_rn(reduce2x2(a01, a23), s_bs1[j0]);
            float c1 = __fadd_rn(reduce2x2(b01, b23), s_bs1[j1]);
            float p0 = m1[2 * p], p1v = m1[2 * p + 1];
            float n0 = __fadd_rn(fmaf(0.9f, p0,  c0), -((p0  > 1.0f) ? 1.0f : 0.0f));
            float n1 = __fadd_rn(fmaf(0.9f, p1v, c1), -((p1v > 1.0f) ? 1.0f : 0.0f));
            m1[2 * p] = n0; m1[2 * p + 1] = n1;
            bits1 |= ((n0 > 1.0f) ? 1u : 0u) << j0;
            bits1 |= ((n1 > 1.0f) ? 1u : 0u) << j1;
        }
        s_b1[tid] = bits1;
        __syncthreads();
        bits1 |= s_b1[tid ^ 32];

        float spk1r[28];
        #pragma unroll
        for (int i = 0; i < 28; i++) spk1r[i] = ((bits1 >> i) & 1u) ? 1.0f : 0.0f;

        // ---- prefetch x for t+1 (xv dead; overlaps s2..ro compute) ----
        {
            int tn = (t + 1 < TT) ? (t + 1) : (TT - 1);
            const ulonglong2* xt2 = (const ulonglong2*)(x + ((size_t)tn * BB + b) * 32);
            #pragma unroll
            for (int i = 0; i < 8; i++) xv[i] = xt2[i];
        }

        // ---- layer s2: my 7 neurons (3 pairs + 1 single) ----
        unsigned bits2 = 0;
        const ulonglong2* v1 = (const ulonglong2*)spk1r;
        #pragma unroll
        for (int p = 0; p < 3; p++) {
            const int j0 = jb2 + 2 * p, j1 = j0 + 1;
            const ulonglong2* wr0 = (const ulonglong2*)&s_ws2[j0 * 28];
            const ulonglong2* wr1 = (const ulonglong2*)&s_ws2[j1 * 28];
            u64 a01 = 0, a23 = 0, b01 = 0, b23 = 0;
            #pragma unroll
            for (int i = 0; i < 7; i++) {
                ulonglong2 w0 = wr0[i];
                ulonglong2 w1 = wr1[i];
                a01 = fma2(w0.x, v1[i].x, a01);  a23 = fma2(w0.y, v1[i].y, a23);
                b01 = fma2(w1.x, v1[i].x, b01);  b23 = fma2(w1.y, v1[i].y, b23);
            }
            float c0 = __fadd_rn(reduce2x2(a01, a23), s_bs2[j0]);
            float c1 = __fadd_rn(reduce2x2(b01, b23), s_bs2[j1]);
            float p0 = m2[2 * p], p1v = m2[2 * p + 1];
            float n0 = __fadd_rn(fmaf(0.9f, p0,  c0), -((p0  > 1.0f) ? 1.0f : 0.0f));
            float n1 = __fadd_rn(fmaf(0.9f, p1v, c1), -((p1v > 1.0f) ? 1.0f : 0.0f));
            m2[2 * p] = n0; m2[2 * p + 1] = n1;
            bits2 |= ((n0 > 1.0f) ? 1u : 0u) << j0;
            bits2 |= ((n1 > 1.0f) ? 1u : 0u) << j1;
        }
        {   // single neuron j = jb2 + 6
            const int j = jb2 + 6;
            const ulonglong2* wr = (const ulonglong2*)&s_ws2[j * 28];
            u64 a01 = 0, a23 = 0;
            #pragma unroll
            for (int i = 0; i < 7; i++) {
                ulonglong2 wv = wr[i];
                a01 = fma2(wv.x, v1[i].x, a01);  a23 = fma2(wv.y, v1[i].y, a23);
            }
            float c = __fadd_rn(reduce2x2(a01, a23), s_bs2[j]);
            float pm = m2[6];
            float n = __fadd_rn(fmaf(0.9f, pm, c), -((pm > 1.0f) ? 1.0f : 0.0f));
            m2[6] = n;
            bits2 |= ((n > 1.0f) ? 1u : 0u) << j;
        }
        s_b2[tid] = bits2;
        __syncthreads();
        bits2 |= s_b2[tid ^ 32];

        float spk2r[14];
        #pragma unroll
        for (int i = 0; i < 14; i++) spk2r[i] = ((bits2 >> i) & 1u) ? 1.0f : 0.0f;

        // ---- layer c1: my 4 neurons (2 pairs); 3 vec groups + tail 12,13 ----
        unsigned bitsc = 0;
        const ulonglong2* v2 = (const ulonglong2*)spk2r;
        #pragma unroll
        for (int p = 0; p < 2; p++) {
            const int j0 = jbc + 2 * p, j1 = j0 + 1;
            const ulonglong2* wr0 = (const ulonglong2*)&s_wc1[j0 * 16];
            const ulonglong2* wr1 = (const ulonglong2*)&s_wc1[j1 * 16];
            u64 a01 = 0, a23 = 0, b01 = 0, b23 = 0;
            #pragma unroll
            for (int i = 0; i < 3; i++) {
                ulonglong2 w0 = wr0[i];
                ulonglong2 w1 = wr1[i];
                a01 = fma2(w0.x, v2[i].x, a01);  a23 = fma2(w0.y, v2[i].y, a23);
                b01 = fma2(w1.x, v2[i].x, b01);  b23 = fma2(w1.y, v2[i].y, b23);
            }
            float s0 = reduce2x2(a01, a23);
            float s1 = reduce2x2(b01, b23);
            s0 = fmaf(s_wc1[j0 * 16 + 12], spk2r[12], s0);
            s0 = fmaf(s_wc1[j0 * 16 + 13], spk2r[13], s0);
            s1 = fmaf(s_wc1[j1 * 16 + 12], spk2r[12], s1);
            s1 = fmaf(s_wc1[j1 * 16 + 13], spk2r[13], s1);
            float c0 = __fadd_rn(s0, s_bc1[j0]);
            float c1 = __fadd_rn(s1, s_bc1[j1]);
            float p0 = mc1[2 * p], p1v = mc1[2 * p + 1];
            float n0 = __fadd_rn(fmaf(0.9f, p0,  c0), -((p0  > 1.0f) ? 1.0f : 0.0f));
            float n1 = __fadd_rn(fmaf(0.9f, p1v, c1), -((p1v > 1.0f) ? 1.0f : 0.0f));
            mc1[2 * p] = n0; mc1[2 * p + 1] = n1;
            bitsc |= ((n0 > 1.0f) ? 1u : 0u) << j0;
            bitsc |= ((n1 > 1.0f) ? 1u : 0u) << j1;
        }
        s_bc[tid] = bitsc;
        __syncthreads();
        bitsc |= s_bc[tid ^ 32];

        float spkcr[8];
        #pragma unroll
        for (int i = 0; i < 8; i++) spkcr[i] = ((bitsc >> i) & 1u) ? 1.0f : 0.0f;

        // ---- layer co (warp0) / ro (warp1) ----
        if (w == 0) {
            const ulonglong2* vc = (const ulonglong2*)spkcr;
            #pragma unroll
            for (int j = 0; j < 3; j++) {
                const ulonglong2* wr = (const ulonglong2*)&s_wco[j * 8];
                u64 a01 = 0, a23 = 0;
                #pragma unroll
                for (int i = 0; i < 2; i++) {
                    ulonglong2 wv = wr[i];
                    a01 = fma2(wv.x, vc[i].x, a01);  a23 = fma2(wv.y, vc[i].y, a23);
                }
                float c = __fadd_rn(reduce2x2(a01, a23), s_bco[j]);
                float m = (j == 0) ? mco0 : (j == 1) ? mco1 : mco2;
                float n = __fadd_rn(fmaf(0.9f, m, c), -((m > 1.0f) ? 1.0f : 0.0f));
                if (j == 0) mco0 = n; else if (j == 1) mco1 = n; else mco2 = n;
            }
            float* pm = o_mco + base * 3;
            pm[0] = mco0; pm[1] = mco1; pm[2] = mco2;
        } else {
            const ulonglong2* wr = (const ulonglong2*)s_wro;
            u64 a01 = 0, a23 = 0;
            #pragma unroll
            for (int i = 0; i < 3; i++) {
                ulonglong2 wv = wr[i];
                a01 = fma2(wv.x, v2[i].x, a01);  a23 = fma2(wv.y, v2[i].y, a23);
            }
            float s = reduce2x2(a01, a23);
            s = fmaf(s_wro[12], spk2r[12], s);
            s = fmaf(s_wro[13], spk2r[13], s);
            float c = __fadd_rn(s, s_bro[0]);
            mro = __fadd_rn(fmaf(0.9f, mro, c), -((mro > 1.0f) ? 1.0f : 0.0f));
            o_mro[base] = mro;
        }

        // ---- spike stores, split across the two warps ----
        {
            // spk1: warp0 stores f4[0..3], warp1 f4[4..6]
            float4* r1 = (float4*)(o_spk1 + base * 28);
            const float4* s1v = (const float4*)spk1r;
            if (w == 0) { r1[0] = s1v[0]; r1[1] = s1v[1]; r1[2] = s1v[2]; r1[3] = s1v[3]; }
            else        { r1[4] = s1v[4]; r1[5] = s1v[5]; r1[6] = s1v[6]; }

            // spk2 (8B-aligned only): warp0 f2[0..3], warp1 f2[4..6]
            float2* r2 = (float2*)(o_spk2 + base * 14);
            const float2* s2v = (const float2*)spk2r;
            if (w == 0) { r2[0] = s2v[0]; r2[1] = s2v[1]; r2[2] = s2v[2]; r2[3] = s2v[3]; }
            else        { r2[4] = s2v[4]; r2[5] = s2v[5]; r2[6] = s2v[6]; }

            // spkc1: one f4 each
            float4* rc = (float4*)(o_spkc1 + base * 8);
            const float4* scv = (const float4*)spkcr;
            rc[w] = scv[w];
        }
    }
}

extern "C" void kernel_launch(void* const* d_in, const int* in_sizes, int n_in,
                              void* d_out, int out_size) {
    snn_kernel<<<BB / 32, 64>>>(
        (const float*)d_in[0],
        (const float*)d_in[1],  (const float*)d_in[2],
        (const float*)d_in[3],  (const float*)d_in[4],
        (const float*)d_in[5],  (const float*)d_in[6],
        (const float*)d_in[7],  (const float*)d_in[8],
        (const float*)d_in[9],  (const float*)d_in[10],
        (float*)d_out);
}